// round 14
// baseline (speedup 1.0000x reference)
#include <cuda_runtime.h>
#include <cuda_fp16.h>
#include <mma.h>

using namespace nvcuda;

#define N_NODES 10000
#define N_EDGES 320000
#define ETOT    330000
#define H       128
#define F_IN    256
#define NEG_SLOPE 0.2f

// ---------------- scratch ----------------------------------------------------
__device__ __half g_h16 [N_NODES * H];  // GEMM output, fp16 (gather source)
__device__ __half g_hn16[N_NODES * H];  // post-GAT relu output, fp16 (GEMM2 A)
__device__ float  g_as [N_NODES];
__device__ float  g_ad [N_NODES];
__device__ int    g_cnt[N_NODES];       // invariant: zero at entry of every call
__device__ int    g_off[N_NODES + 1];
__device__ int    g_rank[ETOT];
__device__ int    g_psrc[ETOT];
__device__ float  g_acc2[2];            // invariant: zero at entry of every call
__device__ int    g_done;               // invariant: zero at entry of every call

// ---------------- histogram + per-edge rank, 4 edges/thread ------------------
__global__ void k_hist(const int* __restrict__ ei) {
    int i = (blockIdx.x * blockDim.x + threadIdx.x) * 4;
    if (i >= ETOT) return;
    if (i < N_EDGES) {
        int4 d4 = *(const int4*)(ei + N_EDGES + i);
        int4 r4;
        r4.x = atomicAdd(&g_cnt[d4.x], 1);
        r4.y = atomicAdd(&g_cnt[d4.y], 1);
        r4.z = atomicAdd(&g_cnt[d4.z], 1);
        r4.w = atomicAdd(&g_cnt[d4.w], 1);
        *(int4*)(g_rank + i) = r4;
    } else {
        int4 r4;
        int d = i - N_EDGES;
        r4.x = atomicAdd(&g_cnt[d + 0], 1);
        r4.y = atomicAdd(&g_cnt[d + 1], 1);
        r4.z = atomicAdd(&g_cnt[d + 2], 1);
        r4.w = atomicAdd(&g_cnt[d + 3], 1);
        *(int4*)(g_rank + i) = r4;
    }
}

// ---------------- scan (warp-shuffle, 1 block x 1024) + g_cnt self-reset -----
__global__ void k_scan() {
    const int CH = 10;
    int t = threadIdx.x;
    int lane = t & 31, wid = t >> 5;
    int base = t * CH;
    int local[CH];
    int sum = 0;
    #pragma unroll
    for (int k = 0; k < CH; k++) {
        int i = base + k;
        int c = (i < N_NODES) ? g_cnt[i] : 0;
        local[k] = sum;
        sum += c;
    }
    int tot = sum;
    int incl = tot;
    #pragma unroll
    for (int o = 1; o < 32; o <<= 1) {
        int v = __shfl_up_sync(0xffffffffu, incl, o);
        if (lane >= o) incl += v;
    }
    __shared__ int wsum[32];
    if (lane == 31) wsum[wid] = incl;
    __syncthreads();
    if (wid == 0) {
        int v = wsum[lane];
        #pragma unroll
        for (int o = 1; o < 32; o <<= 1) {
            int u = __shfl_up_sync(0xffffffffu, v, o);
            if (lane >= o) v += u;
        }
        wsum[lane] = v;
    }
    __syncthreads();
    int excl = incl - tot + (wid > 0 ? wsum[wid - 1] : 0);
    #pragma unroll
    for (int k = 0; k < CH; k++) {
        int i = base + k;
        if (i < N_NODES) {
            g_off[i] = excl + local[k];
            g_cnt[i] = 0;              // restore invariant for next call
        }
    }
    if (t == 0) g_off[N_NODES] = ETOT;
}

__global__ void k_place(const int* __restrict__ ei) {
    int i = (blockIdx.x * blockDim.x + threadIdx.x) * 4;
    if (i >= ETOT) return;
    int4 r4 = *(const int4*)(g_rank + i);
    if (i < N_EDGES) {
        int4 s4 = *(const int4*)(ei + i);
        int4 d4 = *(const int4*)(ei + N_EDGES + i);
        int o0 = g_off[d4.x], o1 = g_off[d4.y], o2 = g_off[d4.z], o3 = g_off[d4.w];
        g_psrc[o0 + r4.x] = s4.x;
        g_psrc[o1 + r4.y] = s4.y;
        g_psrc[o2 + r4.z] = s4.z;
        g_psrc[o3 + r4.w] = s4.w;
    } else {
        int d = i - N_EDGES;
        int o0 = g_off[d + 0], o1 = g_off[d + 1], o2 = g_off[d + 2], o3 = g_off[d + 3];
        g_psrc[o0 + r4.x] = d + 0;
        g_psrc[o1 + r4.y] = d + 1;
        g_psrc[o2 + r4.z] = d + 2;
        g_psrc[o3 + r4.w] = d + 3;
    }
}

// ---------------- wmma GEMM (R8 exact): BM=64, 8 warps, register prefetch ----
#define BM 64
#define BN 128
#define BK 32
#define LDA 40
#define LDB 136
#define LDC 136

__global__ __launch_bounds__(256, 2)
void k_gemm(const float* __restrict__ A32, const float* __restrict__ B,
            const float* __restrict__ att_s, const float* __restrict__ att_d,
            int M, int K) {
    __shared__ char smem_raw[BM * LDC * 4];                // 34816 B
    __half* As = (__half*)smem_raw;                        // [BM][LDA]
    __half* Bs = (__half*)(smem_raw + BM * LDA * 2);       // [BK][LDB]
    float*  Cs = (float*)smem_raw;                         // [BM][LDC] (epilogue)

    int tid  = threadIdx.x;
    int warp = tid >> 5;
    int m0   = blockIdx.x * BM;
    int wr   = (warp >> 1) * 16;   // warp row strip
    int wc   = (warp & 1) * 64;    // warp col half

    int ar = tid >> 2, ac = (tid & 3) * 8;    // A: row 0..63, 8-col seg
    int br = tid >> 3, bc = (tid & 7) * 16;   // B: row 0..31, 16-col seg

    wmma::fragment<wmma::accumulator, 16, 16, 16, float> c[4];
    #pragma unroll
    for (int n = 0; n < 4; n++) wmma::fill_fragment(c[n], 0.0f);

    __half ha[8], hb[16];

    {
        int gm = m0 + ar;
        if (gm < M) {
            if (A32) {
                const float* src = A32 + (size_t)gm * K + ac;
                float4 f0 = *(const float4*)src;
                float4 f1 = *(const float4*)(src + 4);
                ha[0]=__float2half_rn(f0.x); ha[1]=__float2half_rn(f0.y);
                ha[2]=__float2half_rn(f0.z); ha[3]=__float2half_rn(f0.w);
                ha[4]=__float2half_rn(f1.x); ha[5]=__float2half_rn(f1.y);
                ha[6]=__float2half_rn(f1.z); ha[7]=__float2half_rn(f1.w);
            } else {
                *(uint4*)ha = *(const uint4*)(g_hn16 + (size_t)gm * K + ac);
            }
        } else {
            #pragma unroll
            for (int q = 0; q < 8; q++) ha[q] = __float2half_rn(0.f);
        }
        const float* srcb = B + (size_t)br * BN + bc;
        #pragma unroll
        for (int q = 0; q < 4; q++) {
            float4 f = *(const float4*)(srcb + q * 4);
            hb[q*4+0]=__float2half_rn(f.x); hb[q*4+1]=__float2half_rn(f.y);
            hb[q*4+2]=__float2half_rn(f.z); hb[q*4+3]=__float2half_rn(f.w);
        }
    }

    for (int k0 = 0; k0 < K; k0 += BK) {
        *(uint4*)(As + ar * LDA + ac) = *(const uint4*)ha;
        *(uint4*)(Bs + br * LDB + bc)     = *(const uint4*)hb;
        *(uint4*)(Bs + br * LDB + bc + 8) = *(const uint4*)(hb + 8);
        __syncthreads();

        int kn = k0 + BK;
        if (kn < K) {
            int gm = m0 + ar;
            if (gm < M) {
                if (A32) {
                    const float* src = A32 + (size_t)gm * K + kn + ac;
                    float4 f0 = *(const float4*)src;
                    float4 f1 = *(const float4*)(src + 4);
                    ha[0]=__float2half_rn(f0.x); ha[1]=__float2half_rn(f0.y);
                    ha[2]=__float2half_rn(f0.z); ha[3]=__float2half_rn(f0.w);
                    ha[4]=__float2half_rn(f1.x); ha[5]=__float2half_rn(f1.y);
                    ha[6]=__float2half_rn(f1.z); ha[7]=__float2half_rn(f1.w);
                } else {
                    *(uint4*)ha = *(const uint4*)(g_hn16 + (size_t)gm * K + kn + ac);
                }
            } else {
                #pragma unroll
                for (int q = 0; q < 8; q++) ha[q] = __float2half_rn(0.f);
            }
            const float* srcb = B + (size_t)(kn + br) * BN + bc;
            #pragma unroll
            for (int q = 0; q < 4; q++) {
                float4 f = *(const float4*)(srcb + q * 4);
                hb[q*4+0]=__float2half_rn(f.x); hb[q*4+1]=__float2half_rn(f.y);
                hb[q*4+2]=__float2half_rn(f.z); hb[q*4+3]=__float2half_rn(f.w);
            }
        }

        #pragma unroll
        for (int ks = 0; ks < BK; ks += 16) {
            wmma::fragment<wmma::matrix_a, 16, 16, 16, __half, wmma::row_major> a;
            wmma::load_matrix_sync(a, As + wr * LDA + ks, LDA);
            #pragma unroll
            for (int n = 0; n < 4; n++) {
                wmma::fragment<wmma::matrix_b, 16, 16, 16, __half, wmma::row_major> bfr;
                wmma::load_matrix_sync(bfr, Bs + ks * LDB + wc + n * 16, LDB);
                wmma::mma_sync(c[n], a, bfr, c[n]);
            }
        }
        __syncthreads();
    }

    #pragma unroll
    for (int n = 0; n < 4; n++)
        wmma::store_matrix_sync(Cs + wr * LDC + wc + n * 16, c[n], LDC,
                                wmma::mem_row_major);
    __syncthreads();

    {
        int r  = tid >> 2;            // 0..63
        int qd = tid & 3;             // col quarter: qd*32
        int gm = m0 + r;
        const float* crow = Cs + r * LDC + qd * 32;
        float ps = 0.f, pd = 0.f;
        __half hv[32];
        #pragma unroll
        for (int q = 0; q < 32; q += 4) {
            float4 f = *(const float4*)(crow + q);
            int col = qd * 32 + q;
            ps += f.x * att_s[col]     + f.y * att_s[col + 1]
                + f.z * att_s[col + 2] + f.w * att_s[col + 3];
            pd += f.x * att_d[col]     + f.y * att_d[col + 1]
                + f.z * att_d[col + 2] + f.w * att_d[col + 3];
            hv[q + 0] = __float2half_rn(f.x);
            hv[q + 1] = __float2half_rn(f.y);
            hv[q + 2] = __float2half_rn(f.z);
            hv[q + 3] = __float2half_rn(f.w);
        }
        ps += __shfl_xor_sync(0xffffffffu, ps, 1);
        pd += __shfl_xor_sync(0xffffffffu, pd, 1);
        ps += __shfl_xor_sync(0xffffffffu, ps, 2);
        pd += __shfl_xor_sync(0xffffffffu, pd, 2);
        if (gm < M) {
            __half* dst = g_h16 + (size_t)gm * H + qd * 32;
            #pragma unroll
            for (int q = 0; q < 4; q++)
                *(uint4*)(dst + q * 8) = *(const uint4*)(hv + q * 8);
            if (qd == 0) { g_as[gm] = ps; g_ad[gm] = pd; }
        }
    }
}

// ---------------- aggregation: 2 nodes per warp, interleaved 4+4 gathers -----
__device__ __forceinline__ float lrexp(float e) {
    e = e > 0.f ? e : NEG_SLOPE * e;
    return __expf(e);
}

__device__ __forceinline__ float4 h16_load(int a, int lane) {
    uint2 v = *(const uint2*)(g_h16 + (size_t)a * H + lane * 4);
    float2 f0 = __half22float2(*(const __half2*)&v.x);
    float2 f1 = __half22float2(*(const __half2*)&v.y);
    return make_float4(f0.x, f0.y, f1.x, f1.y);
}

// accumulate a batch of 4 edges for one node
__device__ __forceinline__ void agg_batch4(int p, float ad, int lane,
                                           float4& acc, float& z) {
    int idx[4];
    #pragma unroll
    for (int q = 0; q < 4; q++) idx[q] = __ldg(&g_psrc[p + q]);
    float w[4];
    #pragma unroll
    for (int q = 0; q < 4; q++) w[q] = lrexp(g_as[idx[q]] + ad);
    float4 hv[4];
    #pragma unroll
    for (int q = 0; q < 4; q++) hv[q] = h16_load(idx[q], lane);
    #pragma unroll
    for (int q = 0; q < 4; q++) {
        z += w[q];
        acc.x += w[q] * hv[q].x;
        acc.y += w[q] * hv[q].y;
        acc.z += w[q] * hv[q].z;
        acc.w += w[q] * hv[q].w;
    }
}

__device__ __forceinline__ void agg_edge1(int p, float ad, int lane,
                                          float4& acc, float& z) {
    int a0 = __ldg(&g_psrc[p]);
    float w0 = lrexp(g_as[a0] + ad);
    float4 h0 = h16_load(a0, lane);
    z += w0;
    acc.x += w0 * h0.x; acc.y += w0 * h0.y;
    acc.z += w0 * h0.z; acc.w += w0 * h0.w;
}

template<bool TAIL>
__global__ __launch_bounds__(128)
void k_agg(const float* __restrict__ bias,
           const float* __restrict__ Wr, const float* __restrict__ br,
           const float* __restrict__ Wc, const float* __restrict__ bc,
           float* __restrict__ out) {
    int warp = threadIdx.x >> 5;   // 0..3
    int lane = threadIdx.x & 31;
    int n0 = blockIdx.x * 8 + warp * 2;
    int n1 = n0 + 1;
    __shared__ float s0s[8], s1s[8];

    int p0 = g_off[n0], e0 = g_off[n0 + 1];
    int p1 = g_off[n1], e1 = g_off[n1 + 1];
    float ad0 = g_ad[n0], ad1 = g_ad[n1];
    float4 A0 = make_float4(0.f, 0.f, 0.f, 0.f);
    float4 A1 = make_float4(0.f, 0.f, 0.f, 0.f);
    float z0 = 0.f, z1 = 0.f;

    // interleaved main loop: 8 independent gathers in flight (4 per node)
    while (p0 + 4 <= e0 && p1 + 4 <= e1) {
        int ia[4], ib[4];
        #pragma unroll
        for (int q = 0; q < 4; q++) { ia[q] = __ldg(&g_psrc[p0 + q]); }
        #pragma unroll
        for (int q = 0; q < 4; q++) { ib[q] = __ldg(&g_psrc[p1 + q]); }
        float wa[4], wb[4];
        #pragma unroll
        for (int q = 0; q < 4; q++) wa[q] = lrexp(g_as[ia[q]] + ad0);
        #pragma unroll
        for (int q = 0; q < 4; q++) wb[q] = lrexp(g_as[ib[q]] + ad1);
        float4 hva[4], hvb[4];
        #pragma unroll
        for (int q = 0; q < 4; q++) hva[q] = h16_load(ia[q], lane);
        #pragma unroll
        for (int q = 0; q < 4; q++) hvb[q] = h16_load(ib[q], lane);
        #pragma unroll
        for (int q = 0; q < 4; q++) {
            z0 += wa[q];
            A0.x += wa[q] * hva[q].x; A0.y += wa[q] * hva[q].y;
            A0.z += wa[q] * hva[q].z; A0.w += wa[q] * hva[q].w;
            z1 += wb[q];
            A1.x += wb[q] * hvb[q].x; A1.y += wb[q] * hvb[q].y;
            A1.z += wb[q] * hvb[q].z; A1.w += wb[q] * hvb[q].w;
        }
        p0 += 4; p1 += 4;
    }
    // drain node0
    for (; p0 + 4 <= e0; p0 += 4) agg_batch4(p0, ad0, lane, A0, z0);
    for (; p0 < e0; p0++)         agg_edge1 (p0, ad0, lane, A0, z0);
    // drain node1
    for (; p1 + 4 <= e1; p1 += 4) agg_batch4(p1, ad1, lane, A1, z1);
    for (; p1 < e1; p1++)         agg_edge1 (p1, ad1, lane, A1, z1);

    float4 b4 = ((const float4*)bias)[lane];

    #pragma unroll
    for (int k = 0; k < 2; k++) {
        int n      = k ? n1 : n0;
        float4 acc = k ? A1 : A0;
        float  z   = k ? z1 : z0;
        float inv = 1.0f / z;
        float4 v;
        v.x = fmaxf(acc.x * inv + b4.x, 0.f);
        v.y = fmaxf(acc.y * inv + b4.y, 0.f);
        v.z = fmaxf(acc.z * inv + b4.z, 0.f);
        v.w = fmaxf(acc.w * inv + b4.w, 0.f);

        if (!TAIL) {
            __half2 hp[2];
            hp[0] = __floats2half2_rn(v.x, v.y);
            hp[1] = __floats2half2_rn(v.z, v.w);
            *(uint2*)(g_hn16 + (size_t)n * H + lane * 4) = *(const uint2*)hp;
        } else {
            float4 wr = ((const float4*)Wr)[lane];
            float dot = v.x * wr.x + v.y * wr.y + v.z * wr.z + v.w * wr.w;
            #pragma unroll
            for (int o = 16; o; o >>= 1) dot += __shfl_down_sync(0xffffffffu, dot, o);
            if (lane == 0) {
                float r = dot + br[0];
                s0s[warp * 2 + k] = r * Wc[n * 2 + 0];
                s1s[warp * 2 + k] = r * Wc[n * 2 + 1];
            }
        }
    }

    if (TAIL) {
        __syncthreads();
        if (threadIdx.x == 0) {
            float t0 = 0.f, t1 = 0.f;
            #pragma unroll
            for (int q = 0; q < 8; q++) { t0 += s0s[q]; t1 += s1s[q]; }
            atomicAdd(&g_acc2[0], t0);
            atomicAdd(&g_acc2[1], t1);
            __threadfence();
            int old = atomicAdd(&g_done, 1);
            if (old == gridDim.x - 1) {
                g_done = 0;                              // restore invariants
                float r0 = atomicAdd(&g_acc2[0], 0.0f);
                float r1 = atomicAdd(&g_acc2[1], 0.0f);
                g_acc2[0] = 0.0f;
                g_acc2[1] = 0.0f;
                out[0] = r0 + bc[0];
                out[1] = r1 + bc[1];
            }
        }
    }
}

// ---------------- launch -------------------------------------------------------
extern "C" void kernel_launch(void* const* d_in, const int* in_sizes, int n_in,
                              void* d_out, int out_size) {
    const float* x   = (const float*)d_in[0];
    const int*   ei  = (const int*)  d_in[1];
    const float* W1  = (const float*)d_in[2];
    const float* as1 = (const float*)d_in[3];
    const float* ad1 = (const float*)d_in[4];
    const float* b1  = (const float*)d_in[5];
    const float* W2  = (const float*)d_in[6];
    const float* as2 = (const float*)d_in[7];
    const float* ad2 = (const float*)d_in[8];
    const float* b2  = (const float*)d_in[9];
    const float* Wr  = (const float*)d_in[10];
    const float* br  = (const float*)d_in[11];
    const float* Wc  = (const float*)d_in[12];
    const float* bc  = (const float*)d_in[13];
    float* out = (float*)d_out;

    // side stream + events for CSR ∥ GEMM1 overlap (handles created once)
    static cudaStream_t s1 = nullptr;
    static cudaEvent_t ev0 = nullptr, ev1 = nullptr;
    if (s1 == nullptr) {
        cudaStreamCreateWithFlags(&s1, cudaStreamNonBlocking);
        cudaEventCreateWithFlags(&ev0, cudaEventDisableTiming);
        cudaEventCreateWithFlags(&ev1, cudaEventDisableTiming);
    }

    // fork: CSR build on s1
    cudaEventRecord(ev0, 0);
    cudaStreamWaitEvent(s1, ev0, 0);
    k_hist <<<(ETOT / 4 + 255) / 256, 256, 0, s1>>>(ei);
    k_scan <<<1, 1024, 0, s1>>>();
    k_place<<<(ETOT / 4 + 255) / 256, 256, 0, s1>>>(ei);
    cudaEventRecord(ev1, s1);

    int gemm_grid = (N_NODES + BM - 1) / BM;   // 157

    // GEMM1 on main stream, concurrent with CSR build
    k_gemm<<<gemm_grid, 256>>>(x, W1, as1, ad1, N_NODES, F_IN);

    // join
    cudaStreamWaitEvent(0, ev1, 0);

    k_agg<false><<<N_NODES / 8, 128>>>(b1, nullptr, nullptr, nullptr, nullptr, nullptr);

    k_gemm<<<gemm_grid, 256>>>(nullptr, W2, as2, ad2, N_NODES, H);
    k_agg<true><<<N_NODES / 8, 128>>>(b2, Wr, br, Wc, bc, out);
}

// round 15
// speedup vs baseline: 1.1156x; 1.1156x over previous
#include <cuda_runtime.h>
#include <cuda_fp16.h>
#include <mma.h>

using namespace nvcuda;

#define N_NODES 10000
#define N_EDGES 320000
#define ETOT    330000
#define H       128
#define F_IN    256
#define NEG_SLOPE 0.2f

// ---------------- scratch ----------------------------------------------------
__device__ __half g_x16 [N_NODES * F_IN];  // fp16 copy of x (GEMM1 A)
__device__ __half g_h16 [N_NODES * H];     // GEMM output, fp16 (gather source)
__device__ __half g_hn16[N_NODES * H];     // post-GAT relu output (GEMM2 A)
__device__ float  g_as [N_NODES];
__device__ float  g_ad [N_NODES];
__device__ int    g_cnt[N_NODES];          // invariant: zero at entry
__device__ int    g_off[N_NODES + 1];
__device__ int    g_rank[ETOT];
__device__ int    g_psrc[ETOT];
__device__ float  g_acc2[2];               // invariant: zero at entry
__device__ int    g_done;                  // invariant: zero at entry

// ---------------- x fp32 -> fp16 (8 elems/thread, streaming) ------------------
__global__ void k_xconv(const float* __restrict__ x) {
    int i = (blockIdx.x * blockDim.x + threadIdx.x) * 8;
    if (i >= N_NODES * F_IN) return;
    float4 f0 = *(const float4*)(x + i);
    float4 f1 = *(const float4*)(x + i + 4);
    __half h[8];
    h[0]=__float2half_rn(f0.x); h[1]=__float2half_rn(f0.y);
    h[2]=__float2half_rn(f0.z); h[3]=__float2half_rn(f0.w);
    h[4]=__float2half_rn(f1.x); h[5]=__float2half_rn(f1.y);
    h[6]=__float2half_rn(f1.z); h[7]=__float2half_rn(f1.w);
    *(uint4*)(g_x16 + i) = *(const uint4*)h;
}

// ---------------- histogram + per-edge rank, 4 edges/thread ------------------
__global__ void k_hist(const int* __restrict__ ei) {
    int i = (blockIdx.x * blockDim.x + threadIdx.x) * 4;
    if (i >= ETOT) return;
    if (i < N_EDGES) {
        int4 d4 = *(const int4*)(ei + N_EDGES + i);
        int4 r4;
        r4.x = atomicAdd(&g_cnt[d4.x], 1);
        r4.y = atomicAdd(&g_cnt[d4.y], 1);
        r4.z = atomicAdd(&g_cnt[d4.z], 1);
        r4.w = atomicAdd(&g_cnt[d4.w], 1);
        *(int4*)(g_rank + i) = r4;
    } else {
        int4 r4;
        int d = i - N_EDGES;
        r4.x = atomicAdd(&g_cnt[d + 0], 1);
        r4.y = atomicAdd(&g_cnt[d + 1], 1);
        r4.z = atomicAdd(&g_cnt[d + 2], 1);
        r4.w = atomicAdd(&g_cnt[d + 3], 1);
        *(int4*)(g_rank + i) = r4;
    }
}

// ---------------- scan (warp-shuffle, 1 block x 1024) + g_cnt self-reset -----
__global__ void k_scan() {
    const int CH = 10;
    int t = threadIdx.x;
    int lane = t & 31, wid = t >> 5;
    int base = t * CH;
    int local[CH];
    int sum = 0;
    #pragma unroll
    for (int k = 0; k < CH; k++) {
        int i = base + k;
        int c = (i < N_NODES) ? g_cnt[i] : 0;
        local[k] = sum;
        sum += c;
    }
    int tot = sum;
    int incl = tot;
    #pragma unroll
    for (int o = 1; o < 32; o <<= 1) {
        int v = __shfl_up_sync(0xffffffffu, incl, o);
        if (lane >= o) incl += v;
    }
    __shared__ int wsum[32];
    if (lane == 31) wsum[wid] = incl;
    __syncthreads();
    if (wid == 0) {
        int v = wsum[lane];
        #pragma unroll
        for (int o = 1; o < 32; o <<= 1) {
            int u = __shfl_up_sync(0xffffffffu, v, o);
            if (lane >= o) v += u;
        }
        wsum[lane] = v;
    }
    __syncthreads();
    int excl = incl - tot + (wid > 0 ? wsum[wid - 1] : 0);
    #pragma unroll
    for (int k = 0; k < CH; k++) {
        int i = base + k;
        if (i < N_NODES) {
            g_off[i] = excl + local[k];
            g_cnt[i] = 0;              // restore invariant for next call
        }
    }
    if (t == 0) g_off[N_NODES] = ETOT;
}

__global__ void k_place(const int* __restrict__ ei) {
    int i = (blockIdx.x * blockDim.x + threadIdx.x) * 4;
    if (i >= ETOT) return;
    int4 r4 = *(const int4*)(g_rank + i);
    if (i < N_EDGES) {
        int4 s4 = *(const int4*)(ei + i);
        int4 d4 = *(const int4*)(ei + N_EDGES + i);
        int o0 = g_off[d4.x], o1 = g_off[d4.y], o2 = g_off[d4.z], o3 = g_off[d4.w];
        g_psrc[o0 + r4.x] = s4.x;
        g_psrc[o1 + r4.y] = s4.y;
        g_psrc[o2 + r4.z] = s4.z;
        g_psrc[o3 + r4.w] = s4.w;
    } else {
        int d = i - N_EDGES;
        int o0 = g_off[d + 0], o1 = g_off[d + 1], o2 = g_off[d + 2], o3 = g_off[d + 3];
        g_psrc[o0 + r4.x] = d + 0;
        g_psrc[o1 + r4.y] = d + 1;
        g_psrc[o2 + r4.z] = d + 2;
        g_psrc[o3 + r4.w] = d + 3;
    }
}

// ---------------- wmma GEMM (R8 shape): BM=64, 8 warps, fp16 A ---------------
// asel: 0 -> A = g_x16 (K=256), 1 -> A = g_hn16 (K=128)
#define BM 64
#define BN 128
#define BK 32
#define LDA 40
#define LDB 136
#define LDC 136

__global__ __launch_bounds__(256, 2)
void k_gemm(int asel, const float* __restrict__ B,
            const float* __restrict__ att_s, const float* __restrict__ att_d,
            int M, int K) {
    const __half* A16 = asel ? g_hn16 : g_x16;
    __shared__ char smem_raw[BM * LDC * 4];                // 34816 B
    __half* As = (__half*)smem_raw;                        // [BM][LDA]
    __half* Bs = (__half*)(smem_raw + BM * LDA * 2);       // [BK][LDB]
    float*  Cs = (float*)smem_raw;                         // [BM][LDC] (epilogue)

    int tid  = threadIdx.x;
    int warp = tid >> 5;
    int m0   = blockIdx.x * BM;
    int wr   = (warp >> 1) * 16;   // warp row strip
    int wc   = (warp & 1) * 64;    // warp col half

    int ar = tid >> 2, ac = (tid & 3) * 8;    // A: row 0..63, 8-col seg
    int br = tid >> 3, bc = (tid & 7) * 16;   // B: row 0..31, 16-col seg

    wmma::fragment<wmma::accumulator, 16, 16, 16, float> c[4];
    #pragma unroll
    for (int n = 0; n < 4; n++) wmma::fill_fragment(c[n], 0.0f);

    __half ha[8], hb[16];

    {
        int gm = m0 + ar;
        if (gm < M) {
            *(uint4*)ha = *(const uint4*)(A16 + (size_t)gm * K + ac);
        } else {
            #pragma unroll
            for (int q = 0; q < 8; q++) ha[q] = __float2half_rn(0.f);
        }
        const float* srcb = B + (size_t)br * BN + bc;
        #pragma unroll
        for (int q = 0; q < 4; q++) {
            float4 f = *(const float4*)(srcb + q * 4);
            hb[q*4+0]=__float2half_rn(f.x); hb[q*4+1]=__float2half_rn(f.y);
            hb[q*4+2]=__float2half_rn(f.z); hb[q*4+3]=__float2half_rn(f.w);
        }
    }

    for (int k0 = 0; k0 < K; k0 += BK) {
        *(uint4*)(As + ar * LDA + ac) = *(const uint4*)ha;
        *(uint4*)(Bs + br * LDB + bc)     = *(const uint4*)hb;
        *(uint4*)(Bs + br * LDB + bc + 8) = *(const uint4*)(hb + 8);
        __syncthreads();

        int kn = k0 + BK;
        if (kn < K) {
            int gm = m0 + ar;
            if (gm < M) {
                *(uint4*)ha = *(const uint4*)(A16 + (size_t)gm * K + kn + ac);
            } else {
                #pragma unroll
                for (int q = 0; q < 8; q++) ha[q] = __float2half_rn(0.f);
            }
            const float* srcb = B + (size_t)(kn + br) * BN + bc;
            #pragma unroll
            for (int q = 0; q < 4; q++) {
                float4 f = *(const float4*)(srcb + q * 4);
                hb[q*4+0]=__float2half_rn(f.x); hb[q*4+1]=__float2half_rn(f.y);
                hb[q*4+2]=__float2half_rn(f.z); hb[q*4+3]=__float2half_rn(f.w);
            }
        }

        #pragma unroll
        for (int ks = 0; ks < BK; ks += 16) {
            wmma::fragment<wmma::matrix_a, 16, 16, 16, __half, wmma::row_major> a;
            wmma::load_matrix_sync(a, As + wr * LDA + ks, LDA);
            #pragma unroll
            for (int n = 0; n < 4; n++) {
                wmma::fragment<wmma::matrix_b, 16, 16, 16, __half, wmma::row_major> bfr;
                wmma::load_matrix_sync(bfr, Bs + ks * LDB + wc + n * 16, LDB);
                wmma::mma_sync(c[n], a, bfr, c[n]);
            }
        }
        __syncthreads();
    }

    #pragma unroll
    for (int n = 0; n < 4; n++)
        wmma::store_matrix_sync(Cs + wr * LDC + wc + n * 16, c[n], LDC,
                                wmma::mem_row_major);
    __syncthreads();

    {
        int r  = tid >> 2;            // 0..63
        int qd = tid & 3;             // col quarter: qd*32
        int gm = m0 + r;
        const float* crow = Cs + r * LDC + qd * 32;
        float ps = 0.f, pd = 0.f;
        __half hv[32];
        #pragma unroll
        for (int q = 0; q < 32; q += 4) {
            float4 f = *(const float4*)(crow + q);
            int col = qd * 32 + q;
            ps += f.x * att_s[col]     + f.y * att_s[col + 1]
                + f.z * att_s[col + 2] + f.w * att_s[col + 3];
            pd += f.x * att_d[col]     + f.y * att_d[col + 1]
                + f.z * att_d[col + 2] + f.w * att_d[col + 3];
            hv[q + 0] = __float2half_rn(f.x);
            hv[q + 1] = __float2half_rn(f.y);
            hv[q + 2] = __float2half_rn(f.z);
            hv[q + 3] = __float2half_rn(f.w);
        }
        ps += __shfl_xor_sync(0xffffffffu, ps, 1);
        pd += __shfl_xor_sync(0xffffffffu, pd, 1);
        ps += __shfl_xor_sync(0xffffffffu, ps, 2);
        pd += __shfl_xor_sync(0xffffffffu, pd, 2);
        if (gm < M) {
            __half* dst = g_h16 + (size_t)gm * H + qd * 32;
            #pragma unroll
            for (int q = 0; q < 4; q++)
                *(uint4*)(dst + q * 8) = *(const uint4*)(hv + q * 8);
            if (qd == 0) { g_as[gm] = ps; g_ad[gm] = pd; }
        }
    }
}

// ---------------- aggregation (R8 exact): warp per node, unroll 8 ------------
__device__ __forceinline__ float lrexp(float e) {
    e = e > 0.f ? e : NEG_SLOPE * e;
    return __expf(e);
}

__device__ __forceinline__ float4 h16_load(int a, int lane) {
    uint2 v = *(const uint2*)(g_h16 + (size_t)a * H + lane * 4);
    float2 f0 = __half22float2(*(const __half2*)&v.x);
    float2 f1 = __half22float2(*(const __half2*)&v.y);
    return make_float4(f0.x, f0.y, f1.x, f1.y);
}

template<bool TAIL>
__global__ void k_agg(const float* __restrict__ bias,
                      const float* __restrict__ Wr, const float* __restrict__ br,
                      const float* __restrict__ Wc, const float* __restrict__ bc,
                      float* __restrict__ out) {
    int warp = threadIdx.x >> 5;
    int lane = threadIdx.x & 31;
    int n = blockIdx.x * 4 + warp;
    __shared__ float s0s[4], s1s[4];

    int s = g_off[n], e = g_off[n + 1];
    float ad = g_ad[n];
    float4 acc = make_float4(0.f, 0.f, 0.f, 0.f);
    float z = 0.f;

    int p = s;
    for (; p + 8 <= e; p += 8) {
        int idx[8];
        #pragma unroll
        for (int q = 0; q < 8; q++) idx[q] = __ldg(&g_psrc[p + q]);
        float w[8];
        #pragma unroll
        for (int q = 0; q < 8; q++) w[q] = lrexp(g_as[idx[q]] + ad);
        float4 hv[8];
        #pragma unroll
        for (int q = 0; q < 8; q++) hv[q] = h16_load(idx[q], lane);
        #pragma unroll
        for (int q = 0; q < 8; q++) {
            z += w[q];
            acc.x += w[q] * hv[q].x;
            acc.y += w[q] * hv[q].y;
            acc.z += w[q] * hv[q].z;
            acc.w += w[q] * hv[q].w;
        }
    }
    for (; p < e; p++) {
        int a0 = __ldg(&g_psrc[p]);
        float w0 = lrexp(g_as[a0] + ad);
        float4 h0 = h16_load(a0, lane);
        z += w0;
        acc.x += w0 * h0.x; acc.y += w0 * h0.y;
        acc.z += w0 * h0.z; acc.w += w0 * h0.w;
    }

    float inv = 1.0f / z;
    float4 b4 = ((const float4*)bias)[lane];
    float4 v;
    v.x = fmaxf(acc.x * inv + b4.x, 0.f);
    v.y = fmaxf(acc.y * inv + b4.y, 0.f);
    v.z = fmaxf(acc.z * inv + b4.z, 0.f);
    v.w = fmaxf(acc.w * inv + b4.w, 0.f);

    if (!TAIL) {
        __half2 hp[2];
        hp[0] = __floats2half2_rn(v.x, v.y);
        hp[1] = __floats2half2_rn(v.z, v.w);
        *(uint2*)(g_hn16 + (size_t)n * H + lane * 4) = *(const uint2*)hp;
    } else {
        float4 wr = ((const float4*)Wr)[lane];
        float dot = v.x * wr.x + v.y * wr.y + v.z * wr.z + v.w * wr.w;
        #pragma unroll
        for (int o = 16; o; o >>= 1) dot += __shfl_down_sync(0xffffffffu, dot, o);
        if (lane == 0) {
            float r = dot + br[0];
            s0s[warp] = r * Wc[n * 2 + 0];
            s1s[warp] = r * Wc[n * 2 + 1];
        }
        __syncthreads();
        if (threadIdx.x == 0) {
            atomicAdd(&g_acc2[0], s0s[0] + s0s[1] + s0s[2] + s0s[3]);
            atomicAdd(&g_acc2[1], s1s[0] + s1s[1] + s1s[2] + s1s[3]);
            __threadfence();
            int old = atomicAdd(&g_done, 1);
            if (old == gridDim.x - 1) {
                g_done = 0;                              // restore invariants
                float r0 = atomicAdd(&g_acc2[0], 0.0f);
                float r1 = atomicAdd(&g_acc2[1], 0.0f);
                g_acc2[0] = 0.0f;
                g_acc2[1] = 0.0f;
                out[0] = r0 + bc[0];
                out[1] = r1 + bc[1];
            }
        }
    }
}

// ---------------- launch -------------------------------------------------------
extern "C" void kernel_launch(void* const* d_in, const int* in_sizes, int n_in,
                              void* d_out, int out_size) {
    const float* x   = (const float*)d_in[0];
    const int*   ei  = (const int*)  d_in[1];
    const float* W1  = (const float*)d_in[2];
    const float* as1 = (const float*)d_in[3];
    const float* ad1 = (const float*)d_in[4];
    const float* b1  = (const float*)d_in[5];
    const float* W2  = (const float*)d_in[6];
    const float* as2 = (const float*)d_in[7];
    const float* ad2 = (const float*)d_in[8];
    const float* b2  = (const float*)d_in[9];
    const float* Wr  = (const float*)d_in[10];
    const float* br  = (const float*)d_in[11];
    const float* Wc  = (const float*)d_in[12];
    const float* bc  = (const float*)d_in[13];
    float* out = (float*)d_out;

    // side stream + events for CSR ∥ (xconv+GEMM1) overlap (handles created once)
    static cudaStream_t s1 = nullptr;
    static cudaEvent_t ev0 = nullptr, ev1 = nullptr;
    if (s1 == nullptr) {
        cudaStreamCreateWithFlags(&s1, cudaStreamNonBlocking);
        cudaEventCreateWithFlags(&ev0, cudaEventDisableTiming);
        cudaEventCreateWithFlags(&ev1, cudaEventDisableTiming);
    }

    // fork: CSR build on s1
    cudaEventRecord(ev0, 0);
    cudaStreamWaitEvent(s1, ev0, 0);
    k_hist <<<(ETOT / 4 + 255) / 256, 256, 0, s1>>>(ei);
    k_scan <<<1, 1024, 0, s1>>>();
    k_place<<<(ETOT / 4 + 255) / 256, 256, 0, s1>>>(ei);
    cudaEventRecord(ev1, s1);

    int gemm_grid = (N_NODES + BM - 1) / BM;   // 157

    // main stream: x -> fp16, then GEMM1 (concurrent with CSR build on s1)
    k_xconv<<<(N_NODES * F_IN / 8 + 255) / 256, 256>>>(x);
    k_gemm<<<gemm_grid, 256>>>(0, W1, as1, ad1, N_NODES, F_IN);

    // join
    cudaStreamWaitEvent(0, ev1, 0);

    k_agg<false><<<N_NODES / 4, 128>>>(b1, nullptr, nullptr, nullptr, nullptr, nullptr);

    k_gemm<<<gemm_grid, 256>>>(1, W2, as2, ad2, N_NODES, H);
    k_agg<true><<<N_NODES / 4, 128>>>(b2, Wr, br, Wc, bc, out);
}

// round 17
// speedup vs baseline: 1.1219x; 1.0057x over previous
#include <cuda_runtime.h>
#include <cuda_fp16.h>
#include <mma.h>
#include <cstdint>

using namespace nvcuda;

#define N_NODES 10000
#define N_EDGES 320000
#define ETOT    330000
#define H       128
#define F_IN    256
#define NEG_SLOPE 0.2f

#define NX  (N_NODES * F_IN)
#define NW1 (F_IN * H)
#define NW2 (H * H)

// ---------------- scratch ----------------------------------------------------
__device__ __half g_x16 [NX];           // fp16 x (GEMM1 A)
__device__ __half g_w16 [NW1 + NW2];    // fp16 W1 | W2
__device__ __half g_h16 [N_NODES * H];  // GEMM output (gather source)
__device__ __half g_hn16[N_NODES * H];  // post-GAT relu output (GEMM2 A)
__device__ float  g_as [N_NODES];
__device__ float  g_ad [N_NODES];
__device__ int    g_cnt[N_NODES];       // invariant: zero at entry
__device__ int    g_off[N_NODES + 1];
__device__ int    g_rank[ETOT];
__device__ int    g_psrc[ETOT];
__device__ float  g_acc2[2];            // invariant: zero at entry
__device__ int    g_done;               // invariant: zero at entry

// ---------------- fp32 -> fp16 conversion: x | W1 | W2 in one kernel ----------
__global__ void k_conv(const float* __restrict__ x, const float* __restrict__ W1,
                       const float* __restrict__ W2) {
    int i = (blockIdx.x * blockDim.x + threadIdx.x) * 8;
    const float* src;
    __half* dst;
    if (i < NX)                  { src = x + i;               dst = g_x16 + i; }
    else if (i < NX + NW1)       { src = W1 + (i - NX);       dst = g_w16 + (i - NX); }
    else if (i < NX + NW1 + NW2) { src = W2 + (i - NX - NW1); dst = g_w16 + NW1 + (i - NX - NW1); }
    else return;
    float4 f0 = *(const float4*)src;
    float4 f1 = *(const float4*)(src + 4);
    __half h[8];
    h[0]=__float2half_rn(f0.x); h[1]=__float2half_rn(f0.y);
    h[2]=__float2half_rn(f0.z); h[3]=__float2half_rn(f0.w);
    h[4]=__float2half_rn(f1.x); h[5]=__float2half_rn(f1.y);
    h[6]=__float2half_rn(f1.z); h[7]=__float2half_rn(f1.w);
    *(uint4*)dst = *(const uint4*)h;
}

// ---------------- histogram + per-edge rank, 4 edges/thread ------------------
__global__ void k_hist(const int* __restrict__ ei) {
    int i = (blockIdx.x * blockDim.x + threadIdx.x) * 4;
    if (i >= ETOT) return;
    if (i < N_EDGES) {
        int4 d4 = *(const int4*)(ei + N_EDGES + i);
        int4 r4;
        r4.x = atomicAdd(&g_cnt[d4.x], 1);
        r4.y = atomicAdd(&g_cnt[d4.y], 1);
        r4.z = atomicAdd(&g_cnt[d4.z], 1);
        r4.w = atomicAdd(&g_cnt[d4.w], 1);
        *(int4*)(g_rank + i) = r4;
    } else {
        int4 r4;
        int d = i - N_EDGES;
        r4.x = atomicAdd(&g_cnt[d + 0], 1);
        r4.y = atomicAdd(&g_cnt[d + 1], 1);
        r4.z = atomicAdd(&g_cnt[d + 2], 1);
        r4.w = atomicAdd(&g_cnt[d + 3], 1);
        *(int4*)(g_rank + i) = r4;
    }
}

// ---------------- scan (warp-shuffle, 1 block x 1024) + g_cnt self-reset -----
__global__ void k_scan() {
    const int CH = 10;
    int t = threadIdx.x;
    int lane = t & 31, wid = t >> 5;
    int base = t * CH;
    int local[CH];
    int sum = 0;
    #pragma unroll
    for (int k = 0; k < CH; k++) {
        int i = base + k;
        int c = (i < N_NODES) ? g_cnt[i] : 0;
        local[k] = sum;
        sum += c;
    }
    int tot = sum;
    int incl = tot;
    #pragma unroll
    for (int o = 1; o < 32; o <<= 1) {
        int v = __shfl_up_sync(0xffffffffu, incl, o);
        if (lane >= o) incl += v;
    }
    __shared__ int wsum[32];
    if (lane == 31) wsum[wid] = incl;
    __syncthreads();
    if (wid == 0) {
        int v = wsum[lane];
        #pragma unroll
        for (int o = 1; o < 32; o <<= 1) {
            int u = __shfl_up_sync(0xffffffffu, v, o);
            if (lane >= o) v += u;
        }
        wsum[lane] = v;
    }
    __syncthreads();
    int excl = incl - tot + (wid > 0 ? wsum[wid - 1] : 0);
    #pragma unroll
    for (int k = 0; k < CH; k++) {
        int i = base + k;
        if (i < N_NODES) {
            g_off[i] = excl + local[k];
            g_cnt[i] = 0;              // restore invariant for next call
        }
    }
    if (t == 0) g_off[N_NODES] = ETOT;
}

__global__ void k_place(const int* __restrict__ ei) {
    int i = (blockIdx.x * blockDim.x + threadIdx.x) * 4;
    if (i >= ETOT) return;
    int4 r4 = *(const int4*)(g_rank + i);
    if (i < N_EDGES) {
        int4 s4 = *(const int4*)(ei + i);
        int4 d4 = *(const int4*)(ei + N_EDGES + i);
        int o0 = g_off[d4.x], o1 = g_off[d4.y], o2 = g_off[d4.z], o3 = g_off[d4.w];
        g_psrc[o0 + r4.x] = s4.x;
        g_psrc[o1 + r4.y] = s4.y;
        g_psrc[o2 + r4.z] = s4.z;
        g_psrc[o3 + r4.w] = s4.w;
    } else {
        int d = i - N_EDGES;
        int o0 = g_off[d + 0], o1 = g_off[d + 1], o2 = g_off[d + 2], o3 = g_off[d + 3];
        g_psrc[o0 + r4.x] = d + 0;
        g_psrc[o1 + r4.y] = d + 1;
        g_psrc[o2 + r4.z] = d + 2;
        g_psrc[o3 + r4.w] = d + 3;
    }
}

// ---------------- cp.async helpers -------------------------------------------
__device__ __forceinline__ unsigned int smem_u32(const void* p) {
    return (unsigned int)__cvta_generic_to_shared(p);
}
__device__ __forceinline__ void cp16(unsigned int dst, const void* src, int sz) {
    asm volatile("cp.async.cg.shared.global [%0], [%1], 16, %2;"
                 :: "r"(dst), "l"(src), "r"(sz));
}
#define CP_COMMIT() asm volatile("cp.async.commit_group;")
#define CP_WAIT(N)  asm volatile("cp.async.wait_group %0;" :: "n"(N))

// ---------------- wmma GEMM: BM=64, 8 warps, 3-stage cp.async pipeline -------
// asel: 0 -> A=g_x16 (K=256), 1 -> A=g_hn16 (K=128); B = g_w16 (+NW1 if asel)
#define BM 64
#define BN 128
#define BK 32
#define LDA 40       // halves (80B rows, 16B aligned)
#define LDB 136      // halves (272B rows)
#define LDC 136      // floats
#define STAGES 3
#define A_BYTES (BM * LDA * 2)             // 5120
#define B_BYTES (BK * LDB * 2)             // 8704
#define STAGE_BYTES (A_BYTES + B_BYTES)    // 13824
#define SMEM_BYTES (STAGES * STAGE_BYTES)  // 41472 (>= 64*136*4 epilogue)

__global__ __launch_bounds__(256, 2)
void k_gemm(int asel, const float* __restrict__ att_s,
            const float* __restrict__ att_d, int M, int K) {
    const __half* A16 = asel ? g_hn16 : g_x16;
    const __half* B16 = g_w16 + (asel ? NW1 : 0);
    __shared__ char smem_raw[SMEM_BYTES];
    float* Cs = (float*)smem_raw;          // epilogue reuse

    int tid  = threadIdx.x;
    int warp = tid >> 5;
    int m0   = blockIdx.x * BM;
    int wr   = (warp >> 1) * 16;
    int wc   = (warp & 1) * 64;

    int ar = tid >> 2, ac = (tid & 3) * 8;    // A: row 0..63, 8-half (16B) seg
    int br = tid >> 3, bc = (tid & 7) * 16;   // B: row 0..31, 16-half (32B) seg
    int aok = (m0 + ar < M) ? 16 : 0;
    const __half* aSrc = A16 + (size_t)(m0 + ar) * K + ac;
    const __half* bSrc = B16 + (size_t)br * BN + bc;

    const int NIT = K / BK;

    unsigned int sA = smem_u32(smem_raw);
    unsigned int dstA = sA + ar * (LDA * 2) + ac * 2;
    unsigned int dstB = sA + A_BYTES + br * (LDB * 2) + bc * 2;

    wmma::fragment<wmma::accumulator, 16, 16, 16, float> c[4];
    #pragma unroll
    for (int n = 0; n < 4; n++) wmma::fill_fragment(c[n], 0.0f);

    // prefetch stages 0,1
    #pragma unroll
    for (int s = 0; s < STAGES - 1; s++) {
        if (s < NIT) {
            int k0 = s * BK;
            unsigned int off = s * STAGE_BYTES;
            cp16(dstA + off, aSrc + k0, aok);
            cp16(dstB + off,      bSrc + (size_t)k0 * BN,      16);
            cp16(dstB + off + 16, bSrc + (size_t)k0 * BN + 8,  16);
        }
        CP_COMMIT();
    }

    for (int it = 0; it < NIT; it++) {
        if (it + 1 < NIT) { CP_WAIT(1); } else { CP_WAIT(0); }
        __syncthreads();

        // issue stage it+STAGES-1
        int nf = it + STAGES - 1;
        if (nf < NIT) {
            int k0 = nf * BK;
            unsigned int off = (nf % STAGES) * STAGE_BYTES;
            cp16(dstA + off, aSrc + k0, aok);
            cp16(dstB + off,      bSrc + (size_t)k0 * BN,      16);
            cp16(dstB + off + 16, bSrc + (size_t)k0 * BN + 8,  16);
        }
        CP_COMMIT();

        // compute stage it
        const __half* As = (const __half*)(smem_raw + (it % STAGES) * STAGE_BYTES);
        const __half* Bs = (const __half*)(smem_raw + (it % STAGES) * STAGE_BYTES + A_BYTES);
        #pragma unroll
        for (int ks = 0; ks < BK; ks += 16) {
            wmma::fragment<wmma::matrix_a, 16, 16, 16, __half, wmma::row_major> a;
            wmma::load_matrix_sync(a, As + wr * LDA + ks, LDA);
            #pragma unroll
            for (int n = 0; n < 4; n++) {
                wmma::fragment<wmma::matrix_b, 16, 16, 16, __half, wmma::row_major> bfr;
                wmma::load_matrix_sync(bfr, Bs + ks * LDB + wc + n * 16, LDB);
                wmma::mma_sync(c[n], a, bfr, c[n]);
            }
        }
        __syncthreads();   // compute done before next iter's issue overwrites
    }

    // ---- epilogue: frags -> smem fp32, fuse att dots + fp16 store
    #pragma unroll
    for (int n = 0; n < 4; n++)
        wmma::store_matrix_sync(Cs + wr * LDC + wc + n * 16, c[n], LDC,
                                wmma::mem_row_major);
    __syncthreads();

    {
        int r  = tid >> 2;            // 0..63
        int qd = tid & 3;             // col quarter
        int gm = m0 + r;
        const float* crow = Cs + r * LDC + qd * 32;
        float ps = 0.f, pd = 0.f;
        __half hv[32];
        #pragma unroll
        for (int q = 0; q < 32; q += 4) {
            float4 f = *(const float4*)(crow + q);
            int col = qd * 32 + q;
            ps += f.x * att_s[col]     + f.y * att_s[col + 1]
                + f.z * att_s[col + 2] + f.w * att_s[col + 3];
            pd += f.x * att_d[col]     + f.y * att_d[col + 1]
                + f.z * att_d[col + 2] + f.w * att_d[col + 3];
            hv[q + 0] = __float2half_rn(f.x);
            hv[q + 1] = __float2half_rn(f.y);
            hv[q + 2] = __float2half_rn(f.z);
            hv[q + 3] = __float2half_rn(f.w);
        }
        ps += __shfl_xor_sync(0xffffffffu, ps, 1);
        pd += __shfl_xor_sync(0xffffffffu, pd, 1);
        ps += __shfl_xor_sync(0xffffffffu, ps, 2);
        pd += __shfl_xor_sync(0xffffffffu, pd, 2);
        if (gm < M) {
            __half* dst = g_h16 + (size_t)gm * H + qd * 32;
            #pragma unroll
            for (int q = 0; q < 4; q++)
                *(uint4*)(dst + q * 8) = *(const uint4*)(hv + q * 8);
            if (qd == 0) { g_as[gm] = ps; g_ad[gm] = pd; }
        }
    }
}

// ---------------- aggregation (R8 exact): warp per node, unroll 8 ------------
__device__ __forceinline__ float lrexp(float e) {
    e = e > 0.f ? e : NEG_SLOPE * e;
    return __expf(e);
}

__device__ __forceinline__ float4 h16_load(int a, int lane) {
    uint2 v = *(const uint2*)(g_h16 + (size_t)a * H + lane * 4);
    float2 f0 = __half22float2(*(const __half2*)&v.x);
    float2 f1 = __half22float2(*(const __half2*)&v.y);
    return make_float4(f0.x, f0.y, f1.x, f1.y);
}

template<bool TAIL>
__global__ void k_agg(const float* __restrict__ bias,
                      const float* __restrict__ Wr, const float* __restrict__ br,
                      const float* __restrict__ Wc, const float* __restrict__ bc,
                      float* __restrict__ out) {
    int warp = threadIdx.x >> 5;
    int lane = threadIdx.x & 31;
    int n = blockIdx.x * 4 + warp;
    __shared__ float s0s[4], s1s[4];

    int s = g_off[n], e = g_off[n + 1];
    float ad = g_ad[n];
    float4 acc = make_float4(0.f, 0.f, 0.f, 0.f);
    float z = 0.f;

    int p = s;
    for (; p + 8 <= e; p += 8) {
        int idx[8];
        #pragma unroll
        for (int q = 0; q < 8; q++) idx[q] = __ldg(&g_psrc[p + q]);
        float w[8];
        #pragma unroll
        for (int q = 0; q < 8; q++) w[q] = lrexp(g_as[idx[q]] + ad);
        float4 hv[8];
        #pragma unroll
        for (int q = 0; q < 8; q++) hv[q] = h16_load(idx[q], lane);
        #pragma unroll
        for (int q = 0; q < 8; q++) {
            z += w[q];
            acc.x += w[q] * hv[q].x;
            acc.y += w[q] * hv[q].y;
            acc.z += w[q] * hv[q].z;
            acc.w += w[q] * hv[q].w;
        }
    }
    for (; p < e; p++) {
        int a0 = __ldg(&g_psrc[p]);
        float w0 = lrexp(g_as[a0] + ad);
        float4 h0 = h16_load(a0, lane);
        z += w0;
        acc.x += w0 * h0.x; acc.y += w0 * h0.y;
        acc.z += w0 * h0.z; acc.w += w0 * h0.w;
    }

    float inv = 1.0f / z;
    float4 b4 = ((const float4*)bias)[lane];
    float4 v;
    v.x = fmaxf(acc.x * inv + b4.x, 0.f);
    v.y = fmaxf(acc.y * inv + b4.y, 0.f);
    v.z = fmaxf(acc.z * inv + b4.z, 0.f);
    v.w = fmaxf(acc.w * inv + b4.w, 0.f);

    if (!TAIL) {
        __half2 hp[2];
        hp[0] = __floats2half2_rn(v.x, v.y);
        hp[1] = __floats2half2_rn(v.z, v.w);
        *(uint2*)(g_hn16 + (size_t)n * H + lane * 4) = *(const uint2*)hp;
    } else {
        float4 wr = ((const float4*)Wr)[lane];
        float dot = v.x * wr.x + v.y * wr.y + v.z * wr.z + v.w * wr.w;
        #pragma unroll
        for (int o = 16; o; o >>= 1) dot += __shfl_down_sync(0xffffffffu, dot, o);
        if (lane == 0) {
            float r = dot + br[0];
            s0s[warp] = r * Wc[n * 2 + 0];
            s1s[warp] = r * Wc[n * 2 + 1];
        }
        __syncthreads();
        if (threadIdx.x == 0) {
            atomicAdd(&g_acc2[0], s0s[0] + s0s[1] + s0s[2] + s0s[3]);
            atomicAdd(&g_acc2[1], s1s[0] + s1s[1] + s1s[2] + s1s[3]);
            __threadfence();
            int old = atomicAdd(&g_done, 1);
            if (old == gridDim.x - 1) {
                g_done = 0;                              // restore invariants
                float r0 = atomicAdd(&g_acc2[0], 0.0f);
                float r1 = atomicAdd(&g_acc2[1], 0.0f);
                g_acc2[0] = 0.0f;
                g_acc2[1] = 0.0f;
                out[0] = r0 + bc[0];
                out[1] = r1 + bc[1];
            }
        }
    }
}

// ---------------- launch -------------------------------------------------------
extern "C" void kernel_launch(void* const* d_in, const int* in_sizes, int n_in,
                              void* d_out, int out_size) {
    const float* x   = (const float*)d_in[0];
    const int*   ei  = (const int*)  d_in[1];
    const float* W1  = (const float*)d_in[2];
    const float* as1 = (const float*)d_in[3];
    const float* ad1 = (const float*)d_in[4];
    const float* b1  = (const float*)d_in[5];
    const float* W2  = (const float*)d_in[6];
    const float* as2 = (const float*)d_in[7];
    const float* ad2 = (const float*)d_in[8];
    const float* b2  = (const float*)d_in[9];
    const float* Wr  = (const float*)d_in[10];
    const float* br  = (const float*)d_in[11];
    const float* Wc  = (const float*)d_in[12];
    const float* bc  = (const float*)d_in[13];
    float* out = (float*)d_out;

    // side stream + events for CSR ∥ (conv+GEMM1) overlap (handles created once)
    static cudaStream_t s1 = nullptr;
    static cudaEvent_t ev0 = nullptr, ev1 = nullptr;
    if (s1 == nullptr) {
        cudaStreamCreateWithFlags(&s1, cudaStreamNonBlocking);
        cudaEventCreateWithFlags(&ev0, cudaEventDisableTiming);
        cudaEventCreateWithFlags(&ev1, cudaEventDisableTiming);
    }

    // fork: CSR build on s1
    cudaEventRecord(ev0, 0);
    cudaStreamWaitEvent(s1, ev0, 0);
    k_hist <<<(ETOT / 4 + 255) / 256, 256, 0, s1>>>(ei);
    k_scan <<<1, 1024, 0, s1>>>();
    k_place<<<(ETOT / 4 + 255) / 256, 256, 0, s1>>>(ei);
    cudaEventRecord(ev1, s1);

    int gemm_grid = (N_NODES + BM - 1) / BM;   // 157
    int conv_grid = ((NX + NW1 + NW2) / 8 + 255) / 256;

    // main: convert x+W1+W2 -> fp16, then GEMM1 (concurrent with CSR on s1)
    k_conv<<<conv_grid, 256>>>(x, W1, W2);
    k_gemm<<<gemm_grid, 256>>>(0, as1, ad1, N_NODES, F_IN);

    // join
    cudaStreamWaitEvent(0, ev1, 0);

    k_agg<false><<<N_NODES / 4, 128>>>(b1, nullptr, nullptr, nullptr, nullptr, nullptr);

    k_gemm<<<gemm_grid, 256>>>(1, as2, ad2, N_NODES, H);
    k_agg<true><<<N_NODES / 4, 128>>>(b2, Wr, br, Wc, bc, out);
}